// round 13
// baseline (speedup 1.0000x reference)
#include <cuda_runtime.h>
#include <cuda_bf16.h>
#include <math.h>
#include <stdint.h>

#define NN 4096
#define EE 32768
#define BB 64
#define GG 10
#define ZWP 4224      // padded z row stride; real cols 4160, bias slice at 4096
#define NC 4160

__device__ float g_out[NN*64];
__device__ float g_h[NN*64];
__device__ float g_hidden[(size_t)3*EE*64];
__device__ float g_z[(size_t)NN*ZWP];
__device__ float g_agg[NN*64];          // zero-init; root_dgn re-zeroes after use
__device__ float g_m[NN*64];
__device__ float g_s[NN*GG];
__device__ float g_inv[GG*64];
__device__ float g_shift[GG*64];
__device__ float g_gi[NN*192];
__device__ float g_pooled[BB*64];       // head re-zeroes
__device__ float g_psum[1280];          // dgn_fin re-zeroes
__device__ int   g_cntd[NN];
__device__ int   g_cnts[NN];            // scan_src re-zeroes
__device__ int   g_bcnt[BB];            // head re-zeroes
__device__ int   g_soff[NN+1];
__device__ int   g_cur[NN];
__device__ int   g_order[EE];

// ---------- packed f32x2 helpers ----------
__device__ __forceinline__ void fma2(uint64_t& d, uint64_t a, uint64_t b) {
    asm("fma.rn.f32x2 %0, %1, %2, %3;" : "=l"(d) : "l"(a), "l"(b), "l"(d));
}
__device__ __forceinline__ uint64_t splat2(float v) {
    uint64_t r;
    asm("mov.b64 %0, {%1, %1};" : "=l"(r) : "f"(v));
    return r;
}
__device__ __forceinline__ float2 u2f(uint64_t v) {
    float2 r;
    asm("mov.b64 {%0, %1}, %2;" : "=f"(r.x), "=f"(r.y) : "l"(v));
    return r;
}
__device__ __forceinline__ float sigm(float x) { return 1.f / (1.f + expf(-x)); }

// ---------- z GEMM v2: 64 rows x 128 cols per block over flattened 4224-col space ----------
__global__ void zgemm(const float* __restrict__ out, const float* __restrict__ w2,
                      const float* __restrict__ b2, float* __restrict__ z)
{
    extern __shared__ float sm[];
    float* As = sm;            // [64][66]
    float* Bs = sm + 64*66;    // [64][128]
    const int tid = threadIdx.x;   // 128
    const int n0 = blockIdx.x * 64;
    const int c0 = blockIdx.y * 128;
    for (int idx = tid; idx < 4096; idx += 128) {
        int k = idx & 63, r = idx >> 6;
        As[k*66 + r] = out[(size_t)(n0 + r)*64 + k];
    }
    for (int idx = tid; idx < 2048; idx += 128) {
        int c4 = idx & 31, k = idx >> 5;
        int gc = c0 + c4*4;
        float4 v;
        if (gc < 4096) {
            int sl = gc >> 6;
            v = *(const float4*)&w2[sl*4096 + k*64 + (gc & 63)];
        } else if (gc < NC) {
            v = *(const float4*)&b2[k*64 + (gc - 4096)];
        } else v = make_float4(0.f, 0.f, 0.f, 0.f);
        *(float4*)&Bs[k*128 + c4*4] = v;
    }
    __syncthreads();
    const int rg = tid >> 4, cg = tid & 15;   // rows rg*8..+7 (4 pairs), cols cg+16j
    uint64_t acc[4][8];
#pragma unroll
    for (int p = 0; p < 4; p++)
#pragma unroll
        for (int j = 0; j < 8; j++) acc[p][j] = 0ull;
#pragma unroll 4
    for (int k = 0; k < 64; k++) {
        uint64_t a[4];
#pragma unroll
        for (int p = 0; p < 4; p++)
            a[p] = *(const uint64_t*)&As[k*66 + rg*8 + 2*p];
        uint64_t bs[8];
#pragma unroll
        for (int j = 0; j < 8; j++) bs[j] = splat2(Bs[k*128 + cg + 16*j]);
#pragma unroll
        for (int p = 0; p < 4; p++)
#pragma unroll
            for (int j = 0; j < 8; j++) fma2(acc[p][j], a[p], bs[j]);
    }
#pragma unroll
    for (int p = 0; p < 4; p++) {
        int r = n0 + rg*8 + 2*p;
#pragma unroll
        for (int j = 0; j < 8; j++) {
            float2 v = u2f(acc[p][j]);
            size_t c = (size_t)(c0 + cg + 16*j);
            z[(size_t)r*ZWP + c]     = v.x;
            z[(size_t)(r+1)*ZWP + c] = v.y;
        }
    }
}

// ---------- generic small GEMM, f32x2 inner (+DUAL, +GRU gate fuse, +3-layer batch) ----------
template<int K, int J, int TC, bool BT, bool RELU, bool DUAL, bool GRUF, bool B3>
__global__ void gemm_small(const float* __restrict__ A, const float* __restrict__ B,
                           const float* __restrict__ bias,
                           const float* __restrict__ base,
                           float* __restrict__ C, float* __restrict__ C2)
{
    constexpr int KC = 32;
    constexpr int CG = J / TC;       // 16
    constexpr int RG = 256 / CG;     // 16
    constexpr int TR = 64 / RG;      // 4
    constexpr int TR2 = TR / 2;      // 2
    static_assert(RG * CG == 256 && TR == 4, "");
    if (B3) {
        B    += blockIdx.y * K * J;
        bias += blockIdx.y * J;
        C    += (size_t)blockIdx.y * gridDim.x * 64 * J;
    }
    __shared__ float As[KC][66];
    __shared__ float Bs[KC][J + 2];
    __shared__ float bsh[J];
    const int tid = threadIdx.x;
    const int n0 = blockIdx.x * 64;
    const int rg = tid / CG, cg = tid % CG;
    uint64_t acc[TR2][TC];
#pragma unroll
    for (int p = 0; p < TR2; p++)
#pragma unroll
        for (int j = 0; j < TC; j++) acc[p][j] = 0ull;
    for (int j = tid; j < J; j += 256) bsh[j] = bias[j];

    for (int kc = 0; kc < K; kc += KC) {
        __syncthreads();
        for (int idx = tid; idx < 64*KC; idx += 256) {
            int k = idx % KC, r = idx / KC;
            As[k][r] = A[(size_t)(n0 + r) * K + kc + k];
        }
        if (!BT) {
            for (int idx = tid; idx < KC*J; idx += 256) {
                int k = idx / J, j = idx % J;
                Bs[k][j] = B[(kc + k) * J + j];
            }
        } else {
            for (int idx = tid; idx < KC*J; idx += 256) {
                int j = idx / KC, k = idx % KC;
                Bs[k][j] = B[j * K + kc + k];
            }
        }
        __syncthreads();
#pragma unroll 4
        for (int k = 0; k < KC; k++) {
            uint64_t a[TR2];
#pragma unroll
            for (int p = 0; p < TR2; p++)
                a[p] = *(const uint64_t*)&As[k][rg*TR + 2*p];
#pragma unroll
            for (int j = 0; j < TC; j++) {
                int col = GRUF ? ((j >> 2)*64 + cg*4 + (j & 3)) : (cg*TC + j);
                uint64_t bs2 = splat2(Bs[k][col]);
#pragma unroll
                for (int p = 0; p < TR2; p++) fma2(acc[p][j], a[p], bs2);
            }
        }
    }
    if (GRUF) {
        // acc = gh (packed row pairs); base = gi; C = h (in/out); C2 = out (in/out)
#pragma unroll
        for (int p = 0; p < TR2; p++) {
            int r0 = n0 + rg*TR + 2*p;
            const float* gin0 = base + (size_t)r0*192;
            const float* gin1 = gin0 + 192;
#pragma unroll
            for (int q = 0; q < 4; q++) {
                int c = cg*4 + q;
                float2 vr = u2f(acc[p][q]);
                float2 vz = u2f(acc[p][4 + q]);
                float2 vn = u2f(acc[p][8 + q]);
                {
                    float rg_ = sigm(gin0[c] + vr.x + bsh[c]);
                    float zg  = sigm(gin0[64 + c] + vz.x + bsh[64 + c]);
                    float ng  = tanhf(fmaf(rg_, vn.x + bsh[128 + c], gin0[128 + c]));
                    float ho  = C[(size_t)r0*64 + c];
                    float hn  = fmaf(zg, ho, (1.f - zg) * ng);
                    C[(size_t)r0*64 + c]  = hn;
                    C2[(size_t)r0*64 + c] += hn;
                }
                {
                    float rg_ = sigm(gin1[c] + vr.y + bsh[c]);
                    float zg  = sigm(gin1[64 + c] + vz.y + bsh[64 + c]);
                    float ng  = tanhf(fmaf(rg_, vn.y + bsh[128 + c], gin1[128 + c]));
                    float ho  = C[(size_t)(r0+1)*64 + c];
                    float hn  = fmaf(zg, ho, (1.f - zg) * ng);
                    C[(size_t)(r0+1)*64 + c]  = hn;
                    C2[(size_t)(r0+1)*64 + c] += hn;
                }
            }
        }
    } else {
#pragma unroll
        for (int p = 0; p < TR2; p++) {
            int r0 = n0 + rg*TR + 2*p;
#pragma unroll
            for (int j = 0; j < TC; j++) {
                int col = cg*TC + j;
                float2 v = u2f(acc[p][j]);
                float v0 = v.x + bsh[col], v1 = v.y + bsh[col];
                if (RELU) { v0 = fmaxf(v0, 0.f); v1 = fmaxf(v1, 0.f); }
                C[(size_t)r0*J + col]     = v0;
                C[(size_t)(r0+1)*J + col] = v1;
                if (DUAL) {
                    C2[(size_t)r0*J + col]     = v0;
                    C2[(size_t)(r0+1)*J + col] = v1;
                }
            }
        }
    }
}

// ---------- CSR build ----------
__global__ void counts(const int* __restrict__ ei, const int* __restrict__ batch,
                       int* __restrict__ cntd, int* __restrict__ cnts, int* __restrict__ bcnt)
{
    int e = blockIdx.x * 256 + threadIdx.x;
    if (e < EE) {
        atomicAdd(&cnts[ei[e]], 1);
        atomicAdd(&cntd[ei[EE + e]], 1);
    }
    if (e < NN) atomicAdd(&bcnt[batch[e]], 1);
}

__global__ void scan_src(int* __restrict__ cnt, int* __restrict__ off, int* __restrict__ cur)
{
    __shared__ int part[1024];
    const int t = threadIdx.x;
    int c[4]; int s = 0;
#pragma unroll
    for (int i = 0; i < 4; i++) { c[i] = cnt[t*4 + i]; s += c[i]; cnt[t*4 + i] = 0; }
    part[t] = s;
    __syncthreads();
    for (int st = 1; st < 1024; st <<= 1) {
        int v = (t >= st) ? part[t - st] : 0;
        __syncthreads();
        part[t] += v;
        __syncthreads();
    }
    int base = (t > 0) ? part[t - 1] : 0;
#pragma unroll
    for (int i = 0; i < 4; i++) { off[t*4 + i] = base; cur[t*4 + i] = base; base += c[i]; }
    if (t == 1023) off[NN] = part[1023];
}

__global__ void scatter_edges(const int* __restrict__ ei, int* __restrict__ cur,
                              int* __restrict__ order)
{
    int e = blockIdx.x * 256 + threadIdx.x;
    if (e < EE) {
        int p = atomicAdd(&cur[ei[e]], 1);
        order[p] = e;
    }
}

// ---------- edge messages (f32x2 inner) ----------
__global__ void edge_msg_csr(const float* __restrict__ hidden, const float* __restrict__ z,
                             const int* __restrict__ ei, const int* __restrict__ off,
                             const int* __restrict__ order, float* __restrict__ agg)
{
    const int s = blockIdx.x;
    const int beg = off[s], end = off[s + 1];
    if (beg == end) return;
    __shared__ float Zs[NC];
    __shared__ float hsh[8][64];
    const int t = threadIdx.x;
    const float4* zsrc = (const float4*)(z + (size_t)s * ZWP);
    for (int i = t; i < NC/4; i += 256) ((float4*)Zs)[i] = zsrc[i];
    __syncthreads();
    const int w = t >> 5, lane = t & 31;
    for (int idx = beg + w; idx < end; idx += 8) {
        const int e = order[idx];
        hsh[w][lane]      = hidden[(size_t)e*64 + lane];
        hsh[w][lane + 32] = hidden[(size_t)e*64 + 32 + lane];
        __syncwarp();
        uint64_t acc = *(const uint64_t*)&Zs[4096 + 2*lane];   // bias slice
#pragma unroll 8
        for (int k = 0; k < 64; k++)
            fma2(acc, ((const uint64_t*)Zs)[k*32 + lane], splat2(hsh[w][k]));
        float2 v = u2f(acc);
        const int dst = ei[EE + e];
        atomicAdd(&agg[(size_t)dst*64 + 2*lane],     v.x);
        atomicAdd(&agg[(size_t)dst*64 + 2*lane + 1], v.y);
        __syncwarp();
    }
}

// ---------- fused: m = agg/cnt + out@root_w + root_b ; s = softmax(m@lin) ; stats partials ----------
__global__ void root_dgn(const float* __restrict__ out, const float* __restrict__ rw,
                         const float* __restrict__ rb, float* __restrict__ agg,
                         const int* __restrict__ cntd, const float* __restrict__ lin,
                         float* __restrict__ m, float* __restrict__ s, float* __restrict__ psum)
{
    __shared__ float As[64][65];
    __shared__ float Bs[64][64];
    __shared__ float msh[64][65];
    __shared__ float ssh[64][GG];
    __shared__ float lsh[64*GG];
    const int tid = threadIdx.x;   // 256
    const int n0 = blockIdx.x * 64;
    for (int idx = tid; idx < 4096; idx += 256) {
        As[idx % 64][idx / 64] = out[(size_t)(n0 + idx / 64) * 64 + (idx % 64)];
        Bs[idx / 64][idx % 64] = rw[idx];
    }
    for (int i = tid; i < 64*GG; i += 256) lsh[i] = lin[i];
    __syncthreads();
    const int rg = tid >> 4, cg = tid & 15;
    float acc[4][4];
#pragma unroll
    for (int i = 0; i < 4; i++)
#pragma unroll
        for (int j = 0; j < 4; j++) acc[i][j] = 0.f;
#pragma unroll 8
    for (int k = 0; k < 64; k++) {
        float a[4], b[4];
#pragma unroll
        for (int i = 0; i < 4; i++) a[i] = As[k][rg*4 + i];
#pragma unroll
        for (int j = 0; j < 4; j++) b[j] = Bs[k][cg*4 + j];
#pragma unroll
        for (int i = 0; i < 4; i++)
#pragma unroll
            for (int j = 0; j < 4; j++)
                acc[i][j] = fmaf(a[i], b[j], acc[i][j]);
    }
#pragma unroll
    for (int i = 0; i < 4; i++) {
        int lr = rg*4 + i, r = n0 + lr;
        float rs = 1.f / (float)max(cntd[r], 1);
#pragma unroll
        for (int j = 0; j < 4; j++) {
            int col = cg*4 + j;
            float v = acc[i][j] + rb[col] + rs * agg[(size_t)r*64 + col];
            agg[(size_t)r*64 + col] = 0.f;           // self-clean for next layer
            msh[lr][col] = v;
            m[(size_t)r*64 + col] = v;
        }
    }
    __syncthreads();
    if (tid < 64) {
        float logit[GG];
#pragma unroll
        for (int g = 0; g < GG; g++) logit[g] = 0.f;
        for (int k = 0; k < 64; k++) {
            float mv = msh[tid][k];
#pragma unroll
            for (int g = 0; g < GG; g++) logit[g] = fmaf(mv, lsh[k*GG + g], logit[g]);
        }
        float mx = logit[0];
#pragma unroll
        for (int g = 1; g < GG; g++) mx = fmaxf(mx, logit[g]);
        float sum = 0.f;
#pragma unroll
        for (int g = 0; g < GG; g++) { logit[g] = expf(logit[g] - mx); sum += logit[g]; }
        float inv = 1.f / sum;
#pragma unroll
        for (int g = 0; g < GG; g++) {
            float sv = logit[g] * inv;
            ssh[tid][g] = sv;
            s[(size_t)(n0 + tid)*GG + g] = sv;
        }
    }
    __syncthreads();
    for (int c = tid; c < 640; c += 256) {
        int g = c >> 6, dd = c & 63;
        float sum = 0.f, sq = 0.f;
#pragma unroll 8
        for (int r = 0; r < 64; r++) {
            float t = ssh[r][g] * msh[r][dd];
            sum += t;
            sq = fmaf(t, t, sq);
        }
        atomicAdd(&psum[c], sum);
        atomicAdd(&psum[640 + c], sq);
    }
}

__global__ void dgn_fin(const float* __restrict__ gamma, const float* __restrict__ beta,
                        float* __restrict__ psum, float* __restrict__ inv, float* __restrict__ shift)
{
    int c = threadIdx.x;   // 640
    float mu = psum[c] / (float)NN;
    float var = psum[640 + c] / (float)NN - mu*mu;
    float iv = gamma[c] * rsqrtf(var + 1e-5f);
    inv[c] = iv;
    shift[c] = beta[c] - mu * iv;
    psum[c] = 0.f;
    psum[640 + c] = 0.f;
}

// ---------- fused DGN-apply + gi GEMM: gi = dgn(m) @ wih^T + bih ----------
__global__ void gi_dgn(const float* __restrict__ m, const float* __restrict__ s,
                       const float* __restrict__ inv, const float* __restrict__ shift,
                       const float* __restrict__ wih, const float* __restrict__ bih,
                       float* __restrict__ gi)
{
    extern __shared__ float sm[];
    float* As = sm;            // [64][66]
    float* Bs = sm + 64*66;    // [64][194]
    __shared__ float ssh[64*GG];
    __shared__ float ish[GG*64];
    __shared__ float csh[64];
    __shared__ float bsh[192];
    const int tid = threadIdx.x;  // 256
    const int n0 = blockIdx.x * 64;
    for (int i = tid; i < 640; i += 256) {
        ish[i] = inv[i];
        ssh[i] = s[(size_t)n0*GG + i];
    }
    if (tid < 192) bsh[tid] = bih[tid];
    if (tid >= 192) {
        int dd = tid - 192;
        float cs = 0.f;
#pragma unroll
        for (int g = 0; g < GG; g++) cs += shift[g*64 + dd];
        csh[dd] = cs;
    }
    for (int idx = tid; idx < 64*192; idx += 256) {
        int j = idx >> 6, k = idx & 63;
        Bs[k*194 + j] = wih[j*64 + k];
    }
    __syncthreads();
    for (int idx = tid; idx < 4096; idx += 256) {
        int k = idx & 63, r = idx >> 6;
        float mv = m[(size_t)(n0 + r)*64 + k];
        float a = 0.f;
#pragma unroll
        for (int g = 0; g < GG; g++) a = fmaf(ssh[r*GG + g], ish[g*64 + k], a);
        float v = mv + 0.01f * fmaf(mv, a, csh[k]);
        As[k*66 + r] = fmaxf(v, 0.f);
    }
    __syncthreads();
    const int rg = tid >> 4, cg = tid & 15;   // rows rg*4 (2 pairs), cols cg*12..+11
    uint64_t acc[2][12];
#pragma unroll
    for (int p = 0; p < 2; p++)
#pragma unroll
        for (int j = 0; j < 12; j++) acc[p][j] = 0ull;
#pragma unroll 4
    for (int k = 0; k < 64; k++) {
        uint64_t a0 = *(const uint64_t*)&As[k*66 + rg*4];
        uint64_t a1 = *(const uint64_t*)&As[k*66 + rg*4 + 2];
#pragma unroll
        for (int j = 0; j < 12; j++) {
            uint64_t bs2 = splat2(Bs[k*194 + cg*12 + j]);
            fma2(acc[0][j], a0, bs2);
            fma2(acc[1][j], a1, bs2);
        }
    }
#pragma unroll
    for (int p = 0; p < 2; p++) {
        int r = n0 + rg*4 + 2*p;
#pragma unroll
        for (int j = 0; j < 12; j++) {
            int c = cg*12 + j;
            float2 v = u2f(acc[p][j]);
            gi[(size_t)r*192 + c]     = v.x + bsh[c];
            gi[(size_t)(r+1)*192 + c] = v.y + bsh[c];
        }
    }
}

__global__ void pool(const float* __restrict__ out, const int* __restrict__ batch,
                     float* __restrict__ pooled)
{
    int i = blockIdx.x * 256 + threadIdx.x;
    atomicAdd(&pooled[batch[i >> 6]*64 + (i & 63)], out[i]);
}

__global__ void head(float* __restrict__ pooled, int* __restrict__ bcnt,
                     const float* __restrict__ postW, const float* __restrict__ postb,
                     const float* __restrict__ outW, const float* __restrict__ outb,
                     float* __restrict__ y)
{
    const int b = blockIdx.x;
    const int j = threadIdx.x;
    __shared__ float pr[64];
    __shared__ float red[64];
    float invv = 1.f / (float)max(bcnt[b], 1);
    pr[j] = pooled[b*64 + j] * invv;
    pooled[b*64 + j] = 0.f;         // self-clean
    if (j == 0) bcnt[b] = 0;        // self-clean
    __syncthreads();
    float acc = postb[j];
    for (int k = 0; k < 64; k++) acc = fmaf(pr[k], postW[k*64 + j], acc);
    float pv = fmaxf(acc, 0.f) * outW[j];
    red[j] = pv;
    __syncthreads();
    for (int st = 32; st > 0; st >>= 1) {
        if (j < st) red[j] += red[j + st];
        __syncthreads();
    }
    if (j == 0) y[b] = red[0] + outb[0];
}

__global__ void tkl_kernel(const float* __restrict__ preW, const float* __restrict__ preb,
                           const float* __restrict__ postW, const float* __restrict__ postb,
                           const float* __restrict__ outW, const float* __restrict__ outb,
                           float* __restrict__ dst)
{
    const double logc = log(0.15 * sqrt(2.0 * 3.14159265358979323846));
    double acc = 0.0;
    const int tid = threadIdx.x;
    const float* arrs[6] = {preW, preb, postW, postb, outW, outb};
    const int lens[6] = {128*64, 64, 64*64, 64, 64, 1};
    for (int a = 0; a < 6; a++)
        for (int i = tid; i < lens[a]; i += 256) {
            double v = (double)arrs[a][i] / 0.15;
            acc += 0.5 * v * v + logc;
        }
    __shared__ double red[256];
    red[tid] = acc;
    __syncthreads();
    for (int st = 128; st > 0; st >>= 1) {
        if (tid < st) red[tid] += red[tid + st];
        __syncthreads();
    }
    if (tid == 0) dst[0] = (float)red[0];
}

extern "C" void kernel_launch(void* const* d_in, const int* in_sizes, int n_in,
                              void* d_out, int out_size)
{
    const float* x         = (const float*)d_in[0];
    const float* edge_attr = (const float*)d_in[1];
    const float* pre_W     = (const float*)d_in[2];
    const float* pre_b     = (const float*)d_in[3];
    const float* edge_w1   = (const float*)d_in[4];
    const float* edge_b1   = (const float*)d_in[5];
    const float* edge_w2   = (const float*)d_in[6];
    const float* edge_b2   = (const float*)d_in[7];
    const float* root_w    = (const float*)d_in[8];
    const float* root_b    = (const float*)d_in[9];
    const float* gru_wih   = (const float*)d_in[10];
    const float* gru_whh   = (const float*)d_in[11];
    const float* gru_bih   = (const float*)d_in[12];
    const float* gru_bhh   = (const float*)d_in[13];
    const float* gn_lin    = (const float*)d_in[14];
    const float* gn_gamma  = (const float*)d_in[15];
    const float* gn_beta   = (const float*)d_in[16];
    const float* post_W    = (const float*)d_in[17];
    const float* post_b    = (const float*)d_in[18];
    const float* out_W     = (const float*)d_in[19];
    const float* out_b     = (const float*)d_in[20];
    const int*   ei        = (const int*)d_in[21];
    const int*   batch     = (const int*)d_in[22];
    float* y = (float*)d_out;

    float *p_out, *p_h, *p_hidden, *p_z, *p_agg, *p_m, *p_s, *p_inv, *p_shift,
          *p_gi, *p_pooled, *p_psum;
    int *p_cntd, *p_cnts, *p_bcnt, *p_soff, *p_cur, *p_order;
    cudaGetSymbolAddress((void**)&p_out, g_out);
    cudaGetSymbolAddress((void**)&p_h, g_h);
    cudaGetSymbolAddress((void**)&p_hidden, g_hidden);
    cudaGetSymbolAddress((void**)&p_z, g_z);
    cudaGetSymbolAddress((void**)&p_agg, g_agg);
    cudaGetSymbolAddress((void**)&p_m, g_m);
    cudaGetSymbolAddress((void**)&p_s, g_s);
    cudaGetSymbolAddress((void**)&p_inv, g_inv);
    cudaGetSymbolAddress((void**)&p_shift, g_shift);
    cudaGetSymbolAddress((void**)&p_gi, g_gi);
    cudaGetSymbolAddress((void**)&p_pooled, g_pooled);
    cudaGetSymbolAddress((void**)&p_psum, g_psum);
    cudaGetSymbolAddress((void**)&p_cntd, g_cntd);
    cudaGetSymbolAddress((void**)&p_cnts, g_cnts);
    cudaGetSymbolAddress((void**)&p_bcnt, g_bcnt);
    cudaGetSymbolAddress((void**)&p_soff, g_soff);
    cudaGetSymbolAddress((void**)&p_cur, g_cur);
    cudaGetSymbolAddress((void**)&p_order, g_order);

    cudaFuncSetAttribute(zgemm, cudaFuncAttributeMaxDynamicSharedMemorySize, 49664);
    cudaFuncSetAttribute(gi_dgn, cudaFuncAttributeMaxDynamicSharedMemorySize, 66560);

    cudaMemsetAsync(p_cntd, 0, NN * sizeof(int));

    if (out_size >= 65)
        tkl_kernel<<<1, 256>>>(pre_W, pre_b, post_W, post_b, out_W, out_b, y + 64);

    counts<<<EE/256, 256>>>(ei, batch, p_cntd, p_cnts, p_bcnt);
    scan_src<<<1, 1024>>>(p_cnts, p_soff, p_cur);
    scatter_edges<<<EE/256, 256>>>(ei, p_cur, p_order);

    // all 3 layers' hidden = relu(edge_attr @ w1 + b1) in one launch
    gemm_small<64,64,4,false,true,false,false,true><<<dim3(EE/64, 3), 256>>>(
        edge_attr, edge_w1, edge_b1, nullptr, p_hidden, nullptr);

    // pre FC + relu; writes both out and h
    gemm_small<128,64,4,false,true,true,false,false><<<NN/64, 256>>>(
        x, pre_W, pre_b, nullptr, p_out, p_h);

    for (int i = 0; i < 3; i++) {
        const float* w2 = edge_w2 + (size_t)i*64*4096;
        const float* b2 = edge_b2 + (size_t)i*4096;

        zgemm<<<dim3(NN/64, 33), 128, 49664>>>(p_out, w2, b2, p_z);

        edge_msg_csr<<<NN, 256>>>(p_hidden + (size_t)i*EE*64, p_z, ei, p_soff, p_order, p_agg);

        root_dgn<<<NN/64, 256>>>(p_out, root_w + (size_t)i*4096, root_b + (size_t)i*64,
                                 p_agg, p_cntd, gn_lin + (size_t)i*64*GG, p_m, p_s, p_psum);
        dgn_fin<<<1, 640>>>(gn_gamma + (size_t)i*GG*64, gn_beta + (size_t)i*GG*64,
                            p_psum, p_inv, p_shift);

        // gi = dgn(m) @ wih^T + bih (DGN apply fused into A-load)
        gi_dgn<<<NN/64, 256, 66560>>>(p_m, p_s, p_inv, p_shift,
                                      gru_wih + (size_t)i*192*64, gru_bih + (size_t)i*192, p_gi);
        // gh GEMM + GRU gate fused: updates h and out in place
        gemm_small<64,192,12,true,false,false,true,false><<<NN/64, 256>>>(
            p_h, gru_whh + (size_t)i*192*64, gru_bhh + (size_t)i*192,
            p_gi, p_h, p_out);
    }

    pool<<<NN*64/256, 256>>>(p_out, batch, p_pooled);
    head<<<BB, 64>>>(p_pooled, p_bcnt, post_W, post_b, out_W, out_b, y);
}

// round 15
// speedup vs baseline: 1.1203x; 1.1203x over previous
#include <cuda_runtime.h>
#include <cuda_bf16.h>
#include <math.h>
#include <stdint.h>

#define NN 4096
#define EE 32768
#define BB 64
#define GG 10
#define ZWP 4224      // padded z row stride (66*64); real cols = 4160, bias slice at 4096
#define NC 4160

__device__ float g_out[NN*64];
__device__ float g_h[NN*64];
__device__ float g_hidden[(size_t)3*EE*64];
__device__ float g_z[(size_t)NN*ZWP];
__device__ float g_agg[NN*64];
__device__ float g_m[NN*64];
__device__ float g_m2[NN*64];
__device__ float g_s[NN*GG];
__device__ float g_inv[GG*64];
__device__ float g_shift[GG*64];
__device__ float g_gi[NN*192];
__device__ float g_pooled[BB*64];
__device__ float g_psum[1280];      // [0:640) sum, [640:1280) sumsq
__device__ int   g_cntd[NN];
__device__ int   g_cnts[NN];
__device__ int   g_bcnt[BB];
__device__ int   g_soff[NN+1];
__device__ int   g_cur[NN];
__device__ int   g_order[EE];

// ---------- packed f32x2 helpers ----------
__device__ __forceinline__ void fma2(uint64_t& d, uint64_t a, uint64_t b) {
    asm("fma.rn.f32x2 %0, %1, %2, %3;" : "=l"(d) : "l"(a), "l"(b), "l"(d));
}
__device__ __forceinline__ uint64_t splat2(float v) {
    uint64_t r;
    asm("mov.b64 %0, {%1, %1};" : "=l"(r) : "f"(v));
    return r;
}
__device__ __forceinline__ float2 u2f(uint64_t v) {
    float2 r;
    asm("mov.b64 {%0, %1}, %2;" : "=f"(r.x), "=f"(r.y) : "l"(v));
    return r;
}
__device__ __forceinline__ float sigm(float x) { return 1.f / (1.f + expf(-x)); }

// ---------- z GEMM (round-8/10 proven version): z[n, slice, :] = out[n,:] @ w2[slice] ----------
__global__ void zgemm(const float* __restrict__ out, const float* __restrict__ w2,
                      const float* __restrict__ b2, float* __restrict__ z)
{
    __shared__ float As[64][68];
    __shared__ float Bs[64][64];
    const int tid = threadIdx.x;     // 128
    const int n0 = blockIdx.x * 64;
    const int d  = blockIdx.y;
    const float* Bsrc = (d < 64) ? (w2 + d * 4096) : b2;
    for (int idx = tid; idx < 4096; idx += 128) {
        As[idx % 64][idx / 64] = out[(size_t)(n0 + idx / 64) * 64 + (idx % 64)];
        Bs[idx / 64][idx % 64] = Bsrc[idx];
    }
    __syncthreads();
    const int rg = tid >> 4, cg = tid & 15;
    uint64_t acc[4][4];
#pragma unroll
    for (int p = 0; p < 4; p++)
#pragma unroll
        for (int j = 0; j < 4; j++) acc[p][j] = 0ull;
#pragma unroll 8
    for (int k = 0; k < 64; k++) {
        uint64_t a[4];
#pragma unroll
        for (int p = 0; p < 4; p++)
            a[p] = *(const uint64_t*)&As[k][rg*8 + 2*p];
#pragma unroll
        for (int j = 0; j < 4; j++) {
            uint64_t bs = splat2(Bs[k][cg*4 + j]);
#pragma unroll
            for (int p = 0; p < 4; p++) fma2(acc[p][j], a[p], bs);
        }
    }
#pragma unroll
    for (int p = 0; p < 4; p++) {
        float2 v0 = u2f(acc[p][0]), v1 = u2f(acc[p][1]), v2 = u2f(acc[p][2]), v3 = u2f(acc[p][3]);
        size_t r0 = (size_t)(n0 + rg*8 + 2*p) * ZWP + d*64 + cg*4;
        *(float4*)&z[r0]       = make_float4(v0.x, v1.x, v2.x, v3.x);
        *(float4*)&z[r0 + ZWP] = make_float4(v0.y, v1.y, v2.y, v3.y);
    }
}

// ---------- generic small GEMM, f32x2 inner (+DUAL, +GRU gate fuse, +3-layer batch) ----------
template<int K, int J, int TC, bool BT, bool RELU, bool HASBASE, bool DUAL, bool GRUF, bool B3>
__global__ void gemm_small(const float* __restrict__ A, const float* __restrict__ B,
                           const float* __restrict__ bias,
                           const float* __restrict__ base, const int* __restrict__ cnt,
                           float* __restrict__ C, float* __restrict__ C2)
{
    constexpr int KC = 32;
    constexpr int CG = J / TC;       // 16
    constexpr int RG = 256 / CG;     // 16
    constexpr int TR = 64 / RG;      // 4
    constexpr int TR2 = TR / 2;      // 2
    static_assert(RG * CG == 256 && TR == 4, "");
    if (B3) {
        B    += blockIdx.y * K * J;
        bias += blockIdx.y * J;
        C    += (size_t)blockIdx.y * gridDim.x * 64 * J;
    }
    __shared__ float As[KC][66];
    __shared__ float Bs[KC][J + 1];     // J+1: 193/65 mod 32 = 1 -> conflict-free BT staging
    __shared__ float bsh[J];
    const int tid = threadIdx.x;
    const int n0 = blockIdx.x * 64;
    const int rg = tid / CG, cg = tid % CG;
    uint64_t acc[TR2][TC];
#pragma unroll
    for (int p = 0; p < TR2; p++)
#pragma unroll
        for (int j = 0; j < TC; j++) acc[p][j] = 0ull;
    for (int j = tid; j < J; j += 256) bsh[j] = bias[j];

    for (int kc = 0; kc < K; kc += KC) {
        __syncthreads();
        for (int idx = tid; idx < 64*KC; idx += 256) {
            int k = idx % KC, r = idx / KC;
            As[k][r] = A[(size_t)(n0 + r) * K + kc + k];
        }
        if (!BT) {
            for (int idx = tid; idx < KC*J; idx += 256) {
                int k = idx / J, j = idx % J;
                Bs[k][j] = B[(kc + k) * J + j];
            }
        } else {
            for (int idx = tid; idx < KC*J; idx += 256) {
                int j = idx / KC, k = idx % KC;
                Bs[k][j] = B[j * K + kc + k];
            }
        }
        __syncthreads();
#pragma unroll 4
        for (int k = 0; k < KC; k++) {
            uint64_t a[TR2];
#pragma unroll
            for (int p = 0; p < TR2; p++)
                a[p] = *(const uint64_t*)&As[k][rg*TR + 2*p];
#pragma unroll
            for (int j = 0; j < TC; j++) {
                int col = GRUF ? ((j >> 2)*64 + cg*4 + (j & 3)) : (cg*TC + j);
                uint64_t bs2 = splat2(Bs[k][col]);
#pragma unroll
                for (int p = 0; p < TR2; p++) fma2(acc[p][j], a[p], bs2);
            }
        }
    }
    if (GRUF) {
        // acc = gh (row pairs); base = gi; C = h (in/out); C2 = out (in/out)
#pragma unroll
        for (int p = 0; p < TR2; p++) {
            int r0 = n0 + rg*TR + 2*p;
            const float* gin0 = base + (size_t)r0*192;
            const float* gin1 = gin0 + 192;
#pragma unroll
            for (int q = 0; q < 4; q++) {
                int c = cg*4 + q;
                float2 vr = u2f(acc[p][q]);
                float2 vz = u2f(acc[p][4 + q]);
                float2 vn = u2f(acc[p][8 + q]);
                {
                    float rg_ = sigm(gin0[c] + vr.x + bsh[c]);
                    float zg  = sigm(gin0[64 + c] + vz.x + bsh[64 + c]);
                    float ng  = tanhf(fmaf(rg_, vn.x + bsh[128 + c], gin0[128 + c]));
                    float ho  = C[(size_t)r0*64 + c];
                    float hn  = fmaf(zg, ho, (1.f - zg) * ng);
                    C[(size_t)r0*64 + c]  = hn;
                    C2[(size_t)r0*64 + c] += hn;
                }
                {
                    float rg_ = sigm(gin1[c] + vr.y + bsh[c]);
                    float zg  = sigm(gin1[64 + c] + vz.y + bsh[64 + c]);
                    float ng  = tanhf(fmaf(rg_, vn.y + bsh[128 + c], gin1[128 + c]));
                    float ho  = C[(size_t)(r0+1)*64 + c];
                    float hn  = fmaf(zg, ho, (1.f - zg) * ng);
                    C[(size_t)(r0+1)*64 + c]  = hn;
                    C2[(size_t)(r0+1)*64 + c] += hn;
                }
            }
        }
    } else {
#pragma unroll
        for (int p = 0; p < TR2; p++) {
            int r0 = n0 + rg*TR + 2*p;
            float rs0 = HASBASE ? (1.f / (float)max(cnt[r0], 1)) : 0.f;
            float rs1 = HASBASE ? (1.f / (float)max(cnt[r0 + 1], 1)) : 0.f;
#pragma unroll
            for (int j = 0; j < TC; j++) {
                int col = cg*TC + j;
                float2 v = u2f(acc[p][j]);
                float v0 = v.x + bsh[col], v1 = v.y + bsh[col];
                if (HASBASE) {
                    v0 += rs0 * base[(size_t)r0*J + col];
                    v1 += rs1 * base[(size_t)(r0+1)*J + col];
                }
                if (RELU) { v0 = fmaxf(v0, 0.f); v1 = fmaxf(v1, 0.f); }
                C[(size_t)r0*J + col]     = v0;
                C[(size_t)(r0+1)*J + col] = v1;
                if (DUAL) {
                    C2[(size_t)r0*J + col]     = v0;
                    C2[(size_t)(r0+1)*J + col] = v1;
                }
            }
        }
    }
}

// ---------- CSR build ----------
__global__ void counts(const int* __restrict__ ei, const int* __restrict__ batch,
                       int* __restrict__ cntd, int* __restrict__ cnts, int* __restrict__ bcnt)
{
    int e = blockIdx.x * 256 + threadIdx.x;
    if (e < EE) {
        atomicAdd(&cnts[ei[e]], 1);
        atomicAdd(&cntd[ei[EE + e]], 1);
    }
    if (e < NN) atomicAdd(&bcnt[batch[e]], 1);
}

__global__ void scan_src(const int* __restrict__ cnt, int* __restrict__ off, int* __restrict__ cur)
{
    __shared__ int part[1024];
    const int t = threadIdx.x;
    int c[4]; int s = 0;
#pragma unroll
    for (int i = 0; i < 4; i++) { c[i] = cnt[t*4 + i]; s += c[i]; }
    part[t] = s;
    __syncthreads();
    for (int st = 1; st < 1024; st <<= 1) {
        int v = (t >= st) ? part[t - st] : 0;
        __syncthreads();
        part[t] += v;
        __syncthreads();
    }
    int base = (t > 0) ? part[t - 1] : 0;
#pragma unroll
    for (int i = 0; i < 4; i++) { off[t*4 + i] = base; cur[t*4 + i] = base; base += c[i]; }
    if (t == 1023) off[NN] = part[1023];
}

__global__ void scatter_edges(const int* __restrict__ ei, int* __restrict__ cur,
                              int* __restrict__ order)
{
    int e = blockIdx.x * 256 + threadIdx.x;
    if (e < EE) {
        int p = atomicAdd(&cur[ei[e]], 1);
        order[p] = e;
    }
}

// ---------- edge messages (f32x2 inner) ----------
__global__ void edge_msg_csr(const float* __restrict__ hidden, const float* __restrict__ z,
                             const int* __restrict__ ei, const int* __restrict__ off,
                             const int* __restrict__ order, float* __restrict__ agg)
{
    const int s = blockIdx.x;
    const int beg = off[s], end = off[s + 1];
    if (beg == end) return;
    __shared__ float Zs[NC];
    __shared__ float hsh[8][64];
    const int t = threadIdx.x;
    const float4* zsrc = (const float4*)(z + (size_t)s * ZWP);
    for (int i = t; i < NC/4; i += 256) ((float4*)Zs)[i] = zsrc[i];
    __syncthreads();
    const int w = t >> 5, lane = t & 31;
    for (int idx = beg + w; idx < end; idx += 8) {
        const int e = order[idx];
        hsh[w][lane]      = hidden[(size_t)e*64 + lane];
        hsh[w][lane + 32] = hidden[(size_t)e*64 + 32 + lane];
        __syncwarp();
        uint64_t acc = *(const uint64_t*)&Zs[4096 + 2*lane];   // bias slice
#pragma unroll 8
        for (int k = 0; k < 64; k++)
            fma2(acc, ((const uint64_t*)Zs)[k*32 + lane], splat2(hsh[w][k]));
        float2 v = u2f(acc);
        const int dst = ei[EE + e];
        atomicAdd(&agg[(size_t)dst*64 + 2*lane],     v.x);
        atomicAdd(&agg[(size_t)dst*64 + 2*lane + 1], v.y);
        __syncwarp();
    }
}

// ---------- fused: m = agg/cnt + out@root_w + root_b ; s = softmax(m@lin) ; stats partials ----------
__global__ void root_dgn(const float* __restrict__ out, const float* __restrict__ rw,
                         const float* __restrict__ rb, const float* __restrict__ agg,
                         const int* __restrict__ cntd, const float* __restrict__ lin,
                         float* __restrict__ m, float* __restrict__ s, float* __restrict__ psum)
{
    __shared__ float As[64][65];
    __shared__ float Bs[64][64];
    __shared__ float msh[64][65];
    __shared__ float ssh[64][GG];
    __shared__ float lsh[64*GG];
    const int tid = threadIdx.x;   // 256
    const int n0 = blockIdx.x * 64;
    for (int idx = tid; idx < 4096; idx += 256) {
        As[idx % 64][idx / 64] = out[(size_t)(n0 + idx / 64) * 64 + (idx % 64)];
        Bs[idx / 64][idx % 64] = rw[idx];
    }
    for (int i = tid; i < 64*GG; i += 256) lsh[i] = lin[i];
    __syncthreads();
    const int rg = tid >> 4, cg = tid & 15;
    float acc[4][4];
#pragma unroll
    for (int i = 0; i < 4; i++)
#pragma unroll
        for (int j = 0; j < 4; j++) acc[i][j] = 0.f;
#pragma unroll 8
    for (int k = 0; k < 64; k++) {
        float a[4], b[4];
#pragma unroll
        for (int i = 0; i < 4; i++) a[i] = As[k][rg*4 + i];
#pragma unroll
        for (int j = 0; j < 4; j++) b[j] = Bs[k][cg*4 + j];
#pragma unroll
        for (int i = 0; i < 4; i++)
#pragma unroll
            for (int j = 0; j < 4; j++)
                acc[i][j] = fmaf(a[i], b[j], acc[i][j]);
    }
#pragma unroll
    for (int i = 0; i < 4; i++) {
        int lr = rg*4 + i, r = n0 + lr;
        float rs = 1.f / (float)max(cntd[r], 1);
#pragma unroll
        for (int j = 0; j < 4; j++) {
            int col = cg*4 + j;
            float v = acc[i][j] + rb[col] + rs * agg[(size_t)r*64 + col];
            msh[lr][col] = v;
            m[(size_t)r*64 + col] = v;
        }
    }
    __syncthreads();
    if (tid < 64) {
        float logit[GG];
#pragma unroll
        for (int g = 0; g < GG; g++) logit[g] = 0.f;
        for (int k = 0; k < 64; k++) {
            float mv = msh[tid][k];
#pragma unroll
            for (int g = 0; g < GG; g++) logit[g] = fmaf(mv, lsh[k*GG + g], logit[g]);
        }
        float mx = logit[0];
#pragma unroll
        for (int g = 1; g < GG; g++) mx = fmaxf(mx, logit[g]);
        float sum = 0.f;
#pragma unroll
        for (int g = 0; g < GG; g++) { logit[g] = expf(logit[g] - mx); sum += logit[g]; }
        float inv = 1.f / sum;
#pragma unroll
        for (int g = 0; g < GG; g++) {
            float sv = logit[g] * inv;
            ssh[tid][g] = sv;
            s[(size_t)(n0 + tid)*GG + g] = sv;
        }
    }
    __syncthreads();
    for (int c = tid; c < 640; c += 256) {
        int g = c >> 6, dd = c & 63;
        float sum = 0.f, sq = 0.f;
#pragma unroll 8
        for (int r = 0; r < 64; r++) {
            float t = ssh[r][g] * msh[r][dd];
            sum += t;
            sq = fmaf(t, t, sq);
        }
        atomicAdd(&psum[c], sum);
        atomicAdd(&psum[640 + c], sq);
    }
}

__global__ void dgn_fin(const float* __restrict__ gamma, const float* __restrict__ beta,
                        float* __restrict__ psum, float* __restrict__ inv, float* __restrict__ shift)
{
    int c = threadIdx.x;   // 640
    float mu = psum[c] / (float)NN;
    float var = psum[640 + c] / (float)NN - mu*mu;
    float iv = gamma[c] * rsqrtf(var + 1e-5f);
    inv[c] = iv;
    shift[c] = beta[c] - mu * iv;
    psum[c] = 0.f;
    psum[640 + c] = 0.f;
}

__global__ void dgn_apply(const float* __restrict__ m, const float* __restrict__ s,
                          const float* __restrict__ inv, const float* __restrict__ shift,
                          float* __restrict__ m2)
{
    __shared__ float ssh[64*GG];
    __shared__ float ish[GG*64];
    __shared__ float csh[64];
    const int t = threadIdx.x;
    const int n0 = blockIdx.x * 64;
    for (int i = t; i < 64*GG; i += 256) ssh[i] = s[(size_t)n0*GG + i];
    for (int i = t; i < GG*64; i += 256) ish[i] = inv[i];
    if (t < 64) {
        float cs = 0.f;
#pragma unroll
        for (int g = 0; g < GG; g++) cs += shift[g*64 + t];
        csh[t] = cs;
    }
    __syncthreads();
    for (int idx = t; idx < 4096; idx += 256) {
        int nl = idx / 64, dd = idx % 64;
        float a = 0.f;
#pragma unroll
        for (int g = 0; g < GG; g++) a = fmaf(ssh[nl*GG + g], ish[g*64 + dd], a);
        float mv = m[(size_t)(n0 + nl)*64 + dd];
        float v = mv + 0.01f * fmaf(mv, a, csh[dd]);
        m2[(size_t)(n0 + nl)*64 + dd] = fmaxf(v, 0.f);
    }
}

__global__ void pool(const float* __restrict__ out, const int* __restrict__ batch,
                     float* __restrict__ pooled)
{
    int i = blockIdx.x * 256 + threadIdx.x;
    atomicAdd(&pooled[batch[i >> 6]*64 + (i & 63)], out[i]);
}

__global__ void head(const float* __restrict__ pooled, const int* __restrict__ bcnt,
                     const float* __restrict__ postW, const float* __restrict__ postb,
                     const float* __restrict__ outW, const float* __restrict__ outb,
                     float* __restrict__ y)
{
    const int b = blockIdx.x;
    const int j = threadIdx.x;
    __shared__ float pr[64];
    __shared__ float red[64];
    float invv = 1.f / (float)max(bcnt[b], 1);
    pr[j] = pooled[b*64 + j] * invv;
    __syncthreads();
    float acc = postb[j];
    for (int k = 0; k < 64; k++) acc = fmaf(pr[k], postW[k*64 + j], acc);
    float pv = fmaxf(acc, 0.f) * outW[j];
    red[j] = pv;
    __syncthreads();
    for (int st = 32; st > 0; st >>= 1) {
        if (j < st) red[j] += red[j + st];
        __syncthreads();
    }
    if (j == 0) y[b] = red[0] + outb[0];
}

__global__ void tkl_kernel(const float* __restrict__ preW, const float* __restrict__ preb,
                           const float* __restrict__ postW, const float* __restrict__ postb,
                           const float* __restrict__ outW, const float* __restrict__ outb,
                           float* __restrict__ dst)
{
    const double logc = log(0.15 * sqrt(2.0 * 3.14159265358979323846));
    double acc = 0.0;
    const int tid = threadIdx.x;
    const float* arrs[6] = {preW, preb, postW, postb, outW, outb};
    const int lens[6] = {128*64, 64, 64*64, 64, 64, 1};
    for (int a = 0; a < 6; a++)
        for (int i = tid; i < lens[a]; i += 256) {
            double v = (double)arrs[a][i] / 0.15;
            acc += 0.5 * v * v + logc;
        }
    __shared__ double red[256];
    red[tid] = acc;
    __syncthreads();
    for (int st = 128; st > 0; st >>= 1) {
        if (tid < st) red[tid] += red[tid + st];
        __syncthreads();
    }
    if (tid == 0) dst[0] = (float)red[0];
}

extern "C" void kernel_launch(void* const* d_in, const int* in_sizes, int n_in,
                              void* d_out, int out_size)
{
    const float* x         = (const float*)d_in[0];
    const float* edge_attr = (const float*)d_in[1];
    const float* pre_W     = (const float*)d_in[2];
    const float* pre_b     = (const float*)d_in[3];
    const float* edge_w1   = (const float*)d_in[4];
    const float* edge_b1   = (const float*)d_in[5];
    const float* edge_w2   = (const float*)d_in[6];
    const float* edge_b2   = (const float*)d_in[7];
    const float* root_w    = (const float*)d_in[8];
    const float* root_b    = (const float*)d_in[9];
    const float* gru_wih   = (const float*)d_in[10];
    const float* gru_whh   = (const float*)d_in[11];
    const float* gru_bih   = (const float*)d_in[12];
    const float* gru_bhh   = (const float*)d_in[13];
    const float* gn_lin    = (const float*)d_in[14];
    const float* gn_gamma  = (const float*)d_in[15];
    const float* gn_beta   = (const float*)d_in[16];
    const float* post_W    = (const float*)d_in[17];
    const float* post_b    = (const float*)d_in[18];
    const float* out_W     = (const float*)d_in[19];
    const float* out_b     = (const float*)d_in[20];
    const int*   ei        = (const int*)d_in[21];
    const int*   batch     = (const int*)d_in[22];
    float* y = (float*)d_out;

    float *p_out, *p_h, *p_hidden, *p_z, *p_agg, *p_m, *p_m2, *p_s, *p_inv, *p_shift,
          *p_gi, *p_pooled, *p_psum;
    int *p_cntd, *p_cnts, *p_bcnt, *p_soff, *p_cur, *p_order;
    cudaGetSymbolAddress((void**)&p_out, g_out);
    cudaGetSymbolAddress((void**)&p_h, g_h);
    cudaGetSymbolAddress((void**)&p_hidden, g_hidden);
    cudaGetSymbolAddress((void**)&p_z, g_z);
    cudaGetSymbolAddress((void**)&p_agg, g_agg);
    cudaGetSymbolAddress((void**)&p_m, g_m);
    cudaGetSymbolAddress((void**)&p_m2, g_m2);
    cudaGetSymbolAddress((void**)&p_s, g_s);
    cudaGetSymbolAddress((void**)&p_inv, g_inv);
    cudaGetSymbolAddress((void**)&p_shift, g_shift);
    cudaGetSymbolAddress((void**)&p_gi, g_gi);
    cudaGetSymbolAddress((void**)&p_pooled, g_pooled);
    cudaGetSymbolAddress((void**)&p_psum, g_psum);
    cudaGetSymbolAddress((void**)&p_cntd, g_cntd);
    cudaGetSymbolAddress((void**)&p_cnts, g_cnts);
    cudaGetSymbolAddress((void**)&p_bcnt, g_bcnt);
    cudaGetSymbolAddress((void**)&p_soff, g_soff);
    cudaGetSymbolAddress((void**)&p_cur, g_cur);
    cudaGetSymbolAddress((void**)&p_order, g_order);

    cudaMemsetAsync(p_cntd, 0, NN * sizeof(int));
    cudaMemsetAsync(p_cnts, 0, NN * sizeof(int));
    cudaMemsetAsync(p_bcnt, 0, BB * sizeof(int));
    cudaMemsetAsync(p_pooled, 0, BB * 64 * sizeof(float));
    cudaMemsetAsync(p_psum, 0, 1280 * sizeof(float));

    if (out_size >= 65)
        tkl_kernel<<<1, 256>>>(pre_W, pre_b, post_W, post_b, out_W, out_b, y + 64);

    counts<<<EE/256, 256>>>(ei, batch, p_cntd, p_cnts, p_bcnt);
    scan_src<<<1, 1024>>>(p_cnts, p_soff, p_cur);
    scatter_edges<<<EE/256, 256>>>(ei, p_cur, p_order);

    // all 3 layers' hidden = relu(edge_attr @ w1 + b1) in one launch
    gemm_small<64,64,4,false,true,false,false,false,true><<<dim3(EE/64, 3), 256>>>(
        edge_attr, edge_w1, edge_b1, nullptr, nullptr, p_hidden, nullptr);

    // pre FC + relu; writes both out and h
    gemm_small<128,64,4,false,true,false,true,false,false><<<NN/64, 256>>>(
        x, pre_W, pre_b, nullptr, nullptr, p_out, p_h);

    for (int i = 0; i < 3; i++) {
        const float* w2 = edge_w2 + (size_t)i*64*4096;
        const float* b2 = edge_b2 + (size_t)i*4096;

        zgemm<<<dim3(NN/64, 65), 128>>>(p_out, w2, b2, p_z);

        cudaMemsetAsync(p_agg, 0, NN*64*sizeof(float));
        edge_msg_csr<<<NN, 256>>>(p_hidden + (size_t)i*EE*64, p_z, ei, p_soff, p_order, p_agg);

        root_dgn<<<NN/64, 256>>>(p_out, root_w + (size_t)i*4096, root_b + (size_t)i*64,
                                 p_agg, p_cntd, gn_lin + (size_t)i*64*GG, p_m, p_s, p_psum);
        dgn_fin<<<1, 640>>>(gn_gamma + (size_t)i*GG*64, gn_beta + (size_t)i*GG*64,
                            p_psum, p_inv, p_shift);
        dgn_apply<<<NN/64, 256>>>(p_m, p_s, p_inv, p_shift, p_m2);

        // gi = m2 @ wih^T + bih
        gemm_small<64,192,12,true,false,false,false,false,false><<<NN/64, 256>>>(
            p_m2, gru_wih + (size_t)i*192*64, gru_bih + (size_t)i*192,
            nullptr, nullptr, p_gi, nullptr);
        // gh GEMM + GRU gate fused: updates h and out in place
        gemm_small<64,192,12,true,false,false,false,true,false><<<NN/64, 256>>>(
            p_h, gru_whh + (size_t)i*192*64, gru_bhh + (size_t)i*192,
            p_gi, nullptr, p_h, p_out);
    }

    pool<<<NN*64/256, 256>>>(p_out, batch, p_pooled);
    head<<<BB, 64>>>(p_pooled, p_bcnt, post_W, post_b, out_W, out_b, y);
}